// round 15
// baseline (speedup 1.0000x reference)
#include <cuda_runtime.h>
#include <cuda_bf16.h>
#include <cstdint>
#include <cstddef>

#define DIM      512
#define N_NODES  8192
#define N_EDGES  131072   // 2048 paths * 64
#define CAP      128      // per-node edge-bucket capacity (λ≈8, 16x headroom)

// GEMM smem geometry
#define SSTRIDE  40                    // padded bf16 row stride (80 B)
#define TILE_B   (128 * SSTRIDE * 2)   // 10240 B per tile
#define BUF_B    (4 * TILE_B)          // Ah, Al, Bh, Bl = 40960 B
#define GSMEM    (2 * BUF_B)           // double buffered = 81920 B

// ---------------- scratch (device globals; no runtime allocation) ----------
__device__ float         g_q[N_NODES * DIM];      // projected queries, fp32
__device__ __nv_bfloat16 g_BhiT[DIM * DIM];       // Wq^T split hi [n][k]
__device__ __nv_bfloat16 g_BloT[DIM * DIM];       // Wq^T split lo
__device__ int           g_cnt[N_NODES];          // per-node live-edge counts
__device__ int           g_elist[N_NODES * CAP];  // per-node edge buckets

struct Cfg { int idx_is_1; int mask_byte; };
__device__ Cfg g_cfg;

// ---------------- helpers ---------------------------------------------------
__device__ __forceinline__ uint32_t smem_u32(const void* p) {
    uint32_t a;
    asm("{ .reg .u64 t; cvta.to.shared.u64 t, %1; cvt.u32.u64 %0, t; }" : "=r"(a) : "l"(p));
    return a;
}
__device__ __forceinline__ void ldm_x4(uint32_t& r0, uint32_t& r1, uint32_t& r2,
                                       uint32_t& r3, uint32_t addr) {
    asm volatile("ldmatrix.sync.aligned.m8n8.x4.shared.b16 {%0,%1,%2,%3}, [%4];"
                 : "=r"(r0), "=r"(r1), "=r"(r2), "=r"(r3) : "r"(addr));
}
__device__ __forceinline__ void mma_16816(float* c, const uint32_t* a, const uint32_t* b) {
    asm volatile(
        "mma.sync.aligned.m16n8k16.row.col.f32.bf16.bf16.f32 "
        "{%0,%1,%2,%3}, {%4,%5,%6,%7}, {%8,%9}, {%0,%1,%2,%3};"
        : "+f"(c[0]), "+f"(c[1]), "+f"(c[2]), "+f"(c[3])
        : "r"(a[0]), "r"(a[1]), "r"(a[2]), "r"(a[3]), "r"(b[0]), "r"(b[1]));
}
__device__ __forceinline__ float4 ldcs4(const float* p) {
    float4 v;
    asm volatile("ld.global.cs.v4.f32 {%0,%1,%2,%3}, [%4];"
                 : "=f"(v.x), "=f"(v.y), "=f"(v.z), "=f"(v.w) : "l"(p));
    return v;
}

// ---------------- K0: detect idx/mask binding + zero counts ----------------
__global__ __launch_bounds__(256) void detect_kernel(
    const unsigned* __restrict__ c0, const unsigned* __restrict__ c1)
{
    #pragma unroll
    for (int i = 0; i < 32; i++) g_cnt[threadIdx.x + i * 256] = 0;

    __shared__ unsigned sm[2], so[2];
    if (threadIdx.x < 2) { sm[threadIdx.x] = 0u; so[threadIdx.x] = 0u; }
    __syncthreads();
    unsigned m0 = 0, m1 = 0, o0 = 0, o1 = 0;
    for (int i = threadIdx.x; i < 32768; i += 256) {
        unsigned a = c0[i], b = c1[i];
        m0 = max(m0, a); m1 = max(m1, b);
        o0 |= a & 0xFEFEFEFEu; o1 |= b & 0xFEFEFEFEu;
    }
    atomicMax(&sm[0], m0); atomicMax(&sm[1], m1);
    atomicOr (&so[0], o0); atomicOr (&so[1], o1);
    __syncthreads();
    if (threadIdx.x == 0) {
        unsigned M0 = sm[0], M1 = sm[1];
        int idx_is_1;
        if      (M0 <= 1u)                   idx_is_1 = 1;
        else if (M1 <= 1u)                   idx_is_1 = 0;
        else if (M0 < 8192u && M1 >= 8192u)  idx_is_1 = 0;
        else if (M1 < 8192u && M0 >= 8192u)  idx_is_1 = 1;
        else                                 idx_is_1 = 1;
        unsigned Mm = idx_is_1 ? M0 : M1;
        unsigned Om = idx_is_1 ? so[0] : so[1];
        g_cfg.idx_is_1  = idx_is_1;
        g_cfg.mask_byte = (Mm > 1u && Om == 0u) ? 1 : 0;
    }
}
__device__ __forceinline__ bool edge_live(const void* mask, int e, int mask_byte) {
    return mask_byte ? (((const unsigned char*)mask)[e] != 0)
                     : (((const unsigned*)mask)[e] != 0u);
}

// ---------------- K1: build per-node edge buckets (single pass) ------------
__global__ __launch_bounds__(256) void build_kernel(
    const void* __restrict__ c0, const void* __restrict__ c1)
{
    const Cfg cfg = g_cfg;
    const int*  idx  = cfg.idx_is_1 ? (const int*)c1 : (const int*)c0;
    const void* mask = cfg.idx_is_1 ? c0 : c1;
    int e = blockIdx.x * 256 + threadIdx.x;
    if (edge_live(mask, e, cfg.mask_byte)) {
        int node = idx[e];
        int pos  = atomicAdd(&g_cnt[node], 1);
        if (pos < CAP) g_elist[node * CAP + pos] = e;
    }
}

// ---------------- K2: transpose+split Wq -> [n][k] bf16 hi/lo --------------
__global__ __launch_bounds__(256) void conv_wq_kernel(const float* __restrict__ Wq) {
    __shared__ float t[32][33];
    int n0 = blockIdx.x * 32, k0 = blockIdx.y * 32;
    #pragma unroll
    for (int i = 0; i < 4; i++) {
        int lin = threadIdx.x + i * 256;
        int r = lin >> 5, c = lin & 31;
        t[r][c] = Wq[(size_t)(k0 + r) * DIM + n0 + c];
    }
    __syncthreads();
    #pragma unroll
    for (int i = 0; i < 4; i++) {
        int lin = threadIdx.x + i * 256;
        int r = lin >> 5, c = lin & 31;
        float v = t[c][r];
        __nv_bfloat16 h = __float2bfloat16(v);
        __nv_bfloat16 l = __float2bfloat16(v - __bfloat162float(h));
        size_t o = (size_t)(n0 + r) * DIM + k0 + c;
        g_BhiT[o] = h; g_BloT[o] = l;
    }
}

// ---------------- K3: q = prev @ Wq + bq (mma.sync, 16 warps/CTA) ----------
__global__ __launch_bounds__(512, 1) void gemm_mma_kernel(
    const float* __restrict__ Aprev,   // [8192, 512] fp32
    const float* __restrict__ bias, float* __restrict__ C, int bm_base)
{
    extern __shared__ char dsm[];

    const int tid = threadIdx.x, wid = tid >> 5, lane = tid & 31;
    const int wm = wid & 3, wn = wid >> 2;          // 4(M) x 4(N)
    const int bm = blockIdx.y + bm_base, bn = blockIdx.x;

    const float* Asrc = Aprev + (size_t)bm * 128 * DIM;
    const __nv_bfloat16* Bh = g_BhiT + (size_t)bn * 128 * DIM;
    const __nv_bfloat16* Bl = g_BloT + (size_t)bn * 128 * DIM;

    float acc[2][4][4];
    #pragma unroll
    for (int i = 0; i < 2; i++)
        #pragma unroll
        for (int j = 0; j < 4; j++)
            #pragma unroll
            for (int k = 0; k < 4; k++) acc[i][j][k] = 0.f;

    const uint32_t a_row = lane & 15, a_c8 = (lane >> 4) << 3;
    const uint32_t b_n   = (lane & 7) + ((lane >> 4) << 3);
    const uint32_t b_k8  = ((lane >> 3) & 1) << 3;
    const uint32_t sbase = smem_u32(dsm);
    const uint32_t offA0 = 0 * TILE_B + (wm * 32 + a_row) * (SSTRIDE * 2) + a_c8 * 2;
    const uint32_t offA1 = 1 * TILE_B + (wm * 32 + a_row) * (SSTRIDE * 2) + a_c8 * 2;
    const uint32_t offB0 = 2 * TILE_B + (wn * 32 + b_n) * (SSTRIDE * 2) + b_k8 * 2;
    const uint32_t offB1 = 3 * TILE_B + (wn * 32 + b_n) * (SSTRIDE * 2) + b_k8 * 2;

    int ar[2], ac[2];
    #pragma unroll
    for (int i = 0; i < 2; i++) {
        int l = tid + i * 512;
        ar[i] = l >> 3; ac[i] = (l & 7) * 4;
    }
    const int br = tid >> 2, bc = (tid & 3) * 8;

    float4 pa[2];
    uint4  pb[2];
    #pragma unroll
    for (int i = 0; i < 2; i++)
        pa[i] = *(const float4*)(Asrc + (size_t)ar[i] * DIM + ac[i]);
    pb[0] = *(const uint4*)(Bh + (size_t)br * DIM + bc);
    pb[1] = *(const uint4*)(Bl + (size_t)br * DIM + bc);

    for (int ch = 0; ch < 16; ch++) {
        char* buf = dsm + (ch & 1) * BUF_B;
        #pragma unroll
        for (int i = 0; i < 2; i++) {
            float4 v = pa[i];
            __nv_bfloat16 h0 = __float2bfloat16(v.x), h1 = __float2bfloat16(v.y);
            __nv_bfloat16 h2 = __float2bfloat16(v.z), h3 = __float2bfloat16(v.w);
            __nv_bfloat16 l0 = __float2bfloat16(v.x - __bfloat162float(h0));
            __nv_bfloat16 l1 = __float2bfloat16(v.y - __bfloat162float(h1));
            __nv_bfloat16 l2 = __float2bfloat16(v.z - __bfloat162float(h2));
            __nv_bfloat16 l3 = __float2bfloat16(v.w - __bfloat162float(h3));
            uint32_t byo = ar[i] * (SSTRIDE * 2) + ac[i] * 2;
            *(__nv_bfloat162*)(buf + 0 * TILE_B + byo)     = __nv_bfloat162(h0, h1);
            *(__nv_bfloat162*)(buf + 0 * TILE_B + byo + 4) = __nv_bfloat162(h2, h3);
            *(__nv_bfloat162*)(buf + 1 * TILE_B + byo)     = __nv_bfloat162(l0, l1);
            *(__nv_bfloat162*)(buf + 1 * TILE_B + byo + 4) = __nv_bfloat162(l2, l3);
        }
        *(uint4*)(buf + 2 * TILE_B + br * (SSTRIDE * 2) + bc * 2) = pb[0];
        *(uint4*)(buf + 3 * TILE_B + br * (SSTRIDE * 2) + bc * 2) = pb[1];
        __syncthreads();

        if (ch < 15) {
            const int kb = (ch + 1) * 32;
            #pragma unroll
            for (int i = 0; i < 2; i++)
                pa[i] = *(const float4*)(Asrc + (size_t)ar[i] * DIM + kb + ac[i]);
            pb[0] = *(const uint4*)(Bh + (size_t)br * DIM + kb + bc);
            pb[1] = *(const uint4*)(Bl + (size_t)br * DIM + kb + bc);
        }

        const uint32_t bb = sbase + (ch & 1) * BUF_B;
        #pragma unroll
        for (int ks = 0; ks < 2; ks++) {
            const uint32_t ko = ks * 16 * 2;
            uint32_t ah[2][4], al[2][4], bh[4][2], bl[4][2];
            #pragma unroll
            for (int mi = 0; mi < 2; mi++) {
                uint32_t off = mi * 16 * SSTRIDE * 2 + ko;
                ldm_x4(ah[mi][0], ah[mi][1], ah[mi][2], ah[mi][3], bb + offA0 + off);
                ldm_x4(al[mi][0], al[mi][1], al[mi][2], al[mi][3], bb + offA1 + off);
            }
            #pragma unroll
            for (int nh = 0; nh < 2; nh++) {
                uint32_t off = nh * 16 * SSTRIDE * 2 + ko;
                ldm_x4(bh[nh*2][0], bh[nh*2][1], bh[nh*2+1][0], bh[nh*2+1][1], bb + offB0 + off);
                ldm_x4(bl[nh*2][0], bl[nh*2][1], bl[nh*2+1][0], bl[nh*2+1][1], bb + offB1 + off);
            }
            #pragma unroll
            for (int mi = 0; mi < 2; mi++)
                #pragma unroll
                for (int ni = 0; ni < 4; ni++)
                    mma_16816(acc[mi][ni], ah[mi], bh[ni]);
            #pragma unroll
            for (int mi = 0; mi < 2; mi++)
                #pragma unroll
                for (int ni = 0; ni < 4; ni++)
                    mma_16816(acc[mi][ni], ah[mi], bl[ni]);
            #pragma unroll
            for (int mi = 0; mi < 2; mi++)
                #pragma unroll
                for (int ni = 0; ni < 4; ni++)
                    mma_16816(acc[mi][ni], al[mi], bh[ni]);
        }
    }

    const int qr = lane >> 2, qc = (lane & 3) * 2;
    #pragma unroll
    for (int ni = 0; ni < 4; ni++) {
        int col = bn * 128 + wn * 32 + ni * 8 + qc;
        float2 b = *(const float2*)(bias + col);
        #pragma unroll
        for (int mi = 0; mi < 2; mi++) {
            int row = bm * 128 + wm * 32 + mi * 16 + qr;
            float2 v0 = make_float2(acc[mi][ni][0] + b.x, acc[mi][ni][1] + b.y);
            float2 v1 = make_float2(acc[mi][ni][2] + b.x, acc[mi][ni][3] + b.y);
            *(float2*)(C + (size_t)row * DIM + col)       = v0;
            *(float2*)(C + (size_t)(row + 8) * DIM + col) = v1;
        }
    }
}

// ---------------- K4a: attn-lite (64 thr, <=64 regs -> 4K regs/CTA) --------
// 2 warps/CTA; small enough to slot into the register hole gemm leaves.
__global__ __launch_bounds__(64, 16) void attn_lite_kernel(
    const float* __restrict__ vals, float* __restrict__ out, int node_base)
{
    int node = node_base + ((blockIdx.x * 64 + threadIdx.x) >> 5);
    int lane = threadIdx.x & 31;

    int cnt = min(g_cnt[node], CAP);
    const int* el = g_elist + node * CAP;

    const float* qp = g_q + (size_t)node * DIM;
    float4 q[4];
    #pragma unroll
    for (int j = 0; j < 4; j++) q[j] = *(const float4*)(qp + lane * 4 + j * 128);

    float m = -1e30f, d = 0.f;
    float4 acc[4];
    #pragma unroll
    for (int j = 0; j < 4; j++) acc[j] = make_float4(0.f, 0.f, 0.f, 0.f);

    for (int p = 0; p < cnt; p++) {
        const float* v = vals + (size_t)el[p] * DIM;
        float4 a[4];
        #pragma unroll
        for (int j = 0; j < 4; j++) a[j] = ldcs4(v + lane * 4 + j * 128);

        float s = 0.f;
        #pragma unroll
        for (int j = 0; j < 4; j++)
            s += a[j].x * q[j].x + a[j].y * q[j].y + a[j].z * q[j].z + a[j].w * q[j].w;
        #pragma unroll
        for (int o = 16; o; o >>= 1) s += __shfl_xor_sync(0xFFFFFFFFu, s, o);

        float mx = fmaxf(m, s);
        float r  = expf(m - mx);
        float w  = expf(s - mx);
        d = d * r + w;
        #pragma unroll
        for (int j = 0; j < 4; j++) {
            acc[j].x = acc[j].x * r + w * a[j].x;
            acc[j].y = acc[j].y * r + w * a[j].y;
            acc[j].z = acc[j].z * r + w * a[j].z;
            acc[j].w = acc[j].w * r + w * a[j].w;
        }
        m = mx;
    }

    float inv = 1.0f / fmaxf(d, 1e-12f);
    float* op = out + (size_t)node * DIM;
    #pragma unroll
    for (int j = 0; j < 4; j++) {
        float4 o = make_float4(acc[j].x * inv, acc[j].y * inv,
                               acc[j].z * inv, acc[j].w * inv);
        *(float4*)(op + lane * 4 + j * 128) = o;
    }
}

// ---------------- K4b: attn paired (full-speed, runs alone) ----------------
__global__ __launch_bounds__(256) void attn_kernel(
    const float* __restrict__ vals, float* __restrict__ out, int node_base)
{
    int node = node_base + ((blockIdx.x * 256 + threadIdx.x) >> 5);
    int lane = threadIdx.x & 31;

    int cnt = min(g_cnt[node], CAP);
    const int* el = g_elist + node * CAP;

    const float* qp = g_q + (size_t)node * DIM;
    float4 q[4];
    #pragma unroll
    for (int j = 0; j < 4; j++) q[j] = *(const float4*)(qp + lane * 4 + j * 128);

    float m = -1e30f, d = 0.f;
    float4 acc[4];
    #pragma unroll
    for (int j = 0; j < 4; j++) acc[j] = make_float4(0.f, 0.f, 0.f, 0.f);

    for (int p = 0; p < cnt; p += 2) {
        const bool has2 = (p + 1 < cnt);
        const float* va = vals + (size_t)el[p] * DIM;
        const float* vb = vals + (size_t)el[has2 ? p + 1 : p] * DIM;

        float4 a[4], b[4];
        #pragma unroll
        for (int j = 0; j < 4; j++) {
            a[j] = ldcs4(va + lane * 4 + j * 128);
            b[j] = ldcs4(vb + lane * 4 + j * 128);
        }

        float sa = 0.f, sb = 0.f;
        #pragma unroll
        for (int j = 0; j < 4; j++) {
            sa += a[j].x * q[j].x + a[j].y * q[j].y + a[j].z * q[j].z + a[j].w * q[j].w;
            sb += b[j].x * q[j].x + b[j].y * q[j].y + b[j].z * q[j].z + b[j].w * q[j].w;
        }
        #pragma unroll
        for (int o = 16; o; o >>= 1) {
            sa += __shfl_xor_sync(0xFFFFFFFFu, sa, o);
            sb += __shfl_xor_sync(0xFFFFFFFFu, sb, o);
        }
        if (!has2) sb = -1e30f;

        float mx = fmaxf(m, fmaxf(sa, sb));
        float r  = expf(m - mx);
        d *= r;
        float wa = expf(sa - mx), wb = expf(sb - mx);
        d += wa + wb;
        #pragma unroll
        for (int j = 0; j < 4; j++) {
            acc[j].x = acc[j].x * r + wa * a[j].x + wb * b[j].x;
            acc[j].y = acc[j].y * r + wa * a[j].y + wb * b[j].y;
            acc[j].z = acc[j].z * r + wa * a[j].z + wb * b[j].z;
            acc[j].w = acc[j].w * r + wa * a[j].w + wb * b[j].w;
        }
        m = mx;
    }

    float inv = 1.0f / fmaxf(d, 1e-12f);
    float* op = out + (size_t)node * DIM;
    #pragma unroll
    for (int j = 0; j < 4; j++) {
        float4 o = make_float4(acc[j].x * inv, acc[j].y * inv,
                               acc[j].z * inv, acc[j].w * inv);
        *(float4*)(op + lane * 4 + j * 128) = o;
    }
}

// ---------------- launch (fork-join with co-resident attn-lite) ------------
extern "C" void kernel_launch(void* const* d_in, const int* in_sizes, int n_in,
                              void* d_out, int out_size)
{
    const float* enc  = nullptr;
    const void*  c0   = nullptr;
    const void*  c1   = nullptr;
    const float* prev = nullptr;
    const float* Wq   = nullptr;
    const float* bq   = nullptr;
    int n131072 = 0;

    for (int i = 0; i < n_in; i++) {
        switch (in_sizes[i]) {
            case 67108864: enc  = (const float*)d_in[i]; break;
            case 4194304:  prev = (const float*)d_in[i]; break;
            case 262144:   Wq   = (const float*)d_in[i]; break;
            case 512:      bq   = (const float*)d_in[i]; break;
            case 131072:
                if (n131072++ == 0) c0 = d_in[i];
                else                c1 = d_in[i];
                break;
            default: break;
        }
    }

    float* out = (float*)d_out;
    float* q;
    cudaGetSymbolAddress((void**)&q, g_q);

    static cudaStream_t s2 = nullptr;
    static cudaEvent_t  evFork, evG0, evG1, evJoin;
    if (!s2) {
        cudaFuncSetAttribute(gemm_mma_kernel,
                             cudaFuncAttributeMaxDynamicSharedMemorySize, GSMEM);
        cudaStreamCreateWithFlags(&s2, cudaStreamNonBlocking);
        cudaEventCreateWithFlags(&evFork, cudaEventDisableTiming);
        cudaEventCreateWithFlags(&evG0,   cudaEventDisableTiming);
        cudaEventCreateWithFlags(&evG1,   cudaEventDisableTiming);
        cudaEventCreateWithFlags(&evJoin, cudaEventDisableTiming);
    }

    // fork: side stream handles edge bucketing (independent of gemm path)
    cudaEventRecord(evFork, 0);
    cudaStreamWaitEvent(s2, evFork, 0);
    detect_kernel<<<1, 256, 0, s2>>>((const unsigned*)c0, (const unsigned*)c1);
    build_kernel<<<N_EDGES / 256, 256, 0, s2>>>(c0, c1);

    // main stream: weight conversion, then the two gemm halves
    conv_wq_kernel<<<dim3(16, 16), 256>>>(Wq);
    dim3 hgrid(DIM / 128, 32);                       // 128 CTAs = ~1 wave
    gemm_mma_kernel<<<hgrid, 512, GSMEM>>>(prev, bq, q, 0);
    cudaEventRecord(evG0, 0);
    gemm_mma_kernel<<<hgrid, 512, GSMEM>>>(prev, bq, q, 32);
    cudaEventRecord(evG1, 0);

    // side stream: tiny attn-lite CTAs (4K regs) co-reside with gemm half 1;
    // paired attn half 1 runs alone afterwards.
    cudaStreamWaitEvent(s2, evG0, 0);
    attn_lite_kernel<<<2048, 64, 0, s2>>>(enc, out, 0);
    cudaStreamWaitEvent(s2, evG1, 0);
    attn_kernel<<<512, 256, 0, s2>>>(enc, out, 4096);

    // join back into the captured origin stream
    cudaEventRecord(evJoin, s2);
    cudaStreamWaitEvent(0, evJoin, 0);
}

// round 16
// speedup vs baseline: 1.0436x; 1.0436x over previous
#include <cuda_runtime.h>
#include <cuda_bf16.h>
#include <cstdint>
#include <cstddef>

#define DIM      512
#define N_NODES  8192
#define N_EDGES  131072   // 2048 paths * 64
#define CAP      128      // per-node edge-bucket capacity

// GEMM smem geometry
#define SSTRIDE  40                    // padded bf16 row stride (80 B)
#define TILE_B   (128 * SSTRIDE * 2)   // 10240 B per tile
#define BUF_B    (4 * TILE_B)          // Ah, Al, Bh, Bl = 40960 B
#define GSMEM    (2 * BUF_B)           // double buffered = 81920 B

// work queue layout
#define WQ_GEMM   256                  // gemm tiles [0,256)
#define WQ_BUILD  512                  // build chunks [256,512), 512 edges each
#define WQ_ATTN   768                  // attn chunks [512,768), 32 nodes each

// ---------------- scratch (device globals; no runtime allocation) ----------
__device__ float         g_q[N_NODES * DIM];
__device__ __nv_bfloat16 g_BhiT[DIM * DIM];
__device__ __nv_bfloat16 g_BloT[DIM * DIM];
__device__ int           g_cnt[N_NODES];
__device__ int           g_elist[N_NODES * CAP];
__device__ int           g_wq;            // global work counter
__device__ int           g_detect;        // detect-done flag
__device__ int           g_build_done;    // completed build chunks
__device__ int           g_done[64];      // per-bm gemm completion (0..4)

struct Cfg { int idx_is_1; int mask_byte; };
__device__ Cfg g_cfg;

// ---------------- helpers ---------------------------------------------------
__device__ __forceinline__ uint32_t smem_u32(const void* p) {
    uint32_t a;
    asm("{ .reg .u64 t; cvta.to.shared.u64 t, %1; cvt.u32.u64 %0, t; }" : "=r"(a) : "l"(p));
    return a;
}
__device__ __forceinline__ void ldm_x4(uint32_t& r0, uint32_t& r1, uint32_t& r2,
                                       uint32_t& r3, uint32_t addr) {
    asm volatile("ldmatrix.sync.aligned.m8n8.x4.shared.b16 {%0,%1,%2,%3}, [%4];"
                 : "=r"(r0), "=r"(r1), "=r"(r2), "=r"(r3) : "r"(addr));
}
__device__ __forceinline__ void mma_16816(float* c, const uint32_t* a, const uint32_t* b) {
    asm volatile(
        "mma.sync.aligned.m16n8k16.row.col.f32.bf16.bf16.f32 "
        "{%0,%1,%2,%3}, {%4,%5,%6,%7}, {%8,%9}, {%0,%1,%2,%3};"
        : "+f"(c[0]), "+f"(c[1]), "+f"(c[2]), "+f"(c[3])
        : "r"(a[0]), "r"(a[1]), "r"(a[2]), "r"(a[3]), "r"(b[0]), "r"(b[1]));
}
__device__ __forceinline__ float4 ldcs4(const float* p) {
    float4 v;
    asm volatile("ld.global.cs.v4.f32 {%0,%1,%2,%3}, [%4];"
                 : "=f"(v.x), "=f"(v.y), "=f"(v.z), "=f"(v.w) : "l"(p));
    return v;
}
__device__ __forceinline__ bool edge_live(const void* mask, int e, int mask_byte) {
    return mask_byte ? (((const unsigned char*)mask)[e] != 0)
                     : (((const unsigned*)mask)[e] != 0u);
}

// ---------------- K0: transpose+split Wq + reset queue state ---------------
__global__ __launch_bounds__(256) void conv_wq_kernel(const float* __restrict__ Wq) {
    if (blockIdx.x == 0 && blockIdx.y == 0) {           // reset fused-kernel state
        if (threadIdx.x == 0) { g_wq = 0; g_detect = 0; g_build_done = 0; }
        if (threadIdx.x < 64) g_done[threadIdx.x] = 0;
    }
    __shared__ float t[32][33];
    int n0 = blockIdx.x * 32, k0 = blockIdx.y * 32;
    #pragma unroll
    for (int i = 0; i < 4; i++) {
        int lin = threadIdx.x + i * 256;
        int r = lin >> 5, c = lin & 31;
        t[r][c] = Wq[(size_t)(k0 + r) * DIM + n0 + c];
    }
    __syncthreads();
    #pragma unroll
    for (int i = 0; i < 4; i++) {
        int lin = threadIdx.x + i * 256;
        int r = lin >> 5, c = lin & 31;
        float v = t[c][r];
        __nv_bfloat16 h = __float2bfloat16(v);
        __nv_bfloat16 l = __float2bfloat16(v - __bfloat162float(h));
        size_t o = (size_t)(n0 + r) * DIM + k0 + c;
        g_BhiT[o] = h; g_BloT[o] = l;
    }
}

// ---------------- device: detect (CTA 0, 512 threads) ----------------------
__device__ void do_detect(const unsigned* __restrict__ c0,
                          const unsigned* __restrict__ c1)
{
    #pragma unroll
    for (int i = 0; i < 16; i++) g_cnt[threadIdx.x + i * 512] = 0;

    __shared__ unsigned sm2[2], so2[2];
    if (threadIdx.x < 2) { sm2[threadIdx.x] = 0u; so2[threadIdx.x] = 0u; }
    __syncthreads();
    unsigned m0 = 0, m1 = 0, o0 = 0, o1 = 0;
    for (int i = threadIdx.x; i < 32768; i += 512) {
        unsigned a = c0[i], b = c1[i];
        m0 = max(m0, a); m1 = max(m1, b);
        o0 |= a & 0xFEFEFEFEu; o1 |= b & 0xFEFEFEFEu;
    }
    atomicMax(&sm2[0], m0); atomicMax(&sm2[1], m1);
    atomicOr (&so2[0], o0); atomicOr (&so2[1], o1);
    __syncthreads();
    if (threadIdx.x == 0) {
        unsigned M0 = sm2[0], M1 = sm2[1];
        int idx_is_1;
        if      (M0 <= 1u)                   idx_is_1 = 1;
        else if (M1 <= 1u)                   idx_is_1 = 0;
        else if (M0 < 8192u && M1 >= 8192u)  idx_is_1 = 0;
        else if (M1 < 8192u && M0 >= 8192u)  idx_is_1 = 1;
        else                                 idx_is_1 = 1;
        unsigned Mm = idx_is_1 ? M0 : M1;
        unsigned Om = idx_is_1 ? so2[0] : so2[1];
        g_cfg.idx_is_1  = idx_is_1;
        g_cfg.mask_byte = (Mm > 1u && Om == 0u) ? 1 : 0;
    }
    __syncthreads();
    __threadfence();
    if (threadIdx.x == 0) atomicExch(&g_detect, 1);
}

// ---------------- device: one gemm tile (existing 16-warp body) ------------
__device__ void gemm_tile(char* dsm, const float* __restrict__ Aprev,
                          const float* __restrict__ bias, float* __restrict__ C,
                          int bm, int bn)
{
    const int tid = threadIdx.x, wid = tid >> 5, lane = tid & 31;
    const int wm = wid & 3, wn = wid >> 2;

    const float* Asrc = Aprev + (size_t)bm * 128 * DIM;
    const __nv_bfloat16* Bh = g_BhiT + (size_t)bn * 128 * DIM;
    const __nv_bfloat16* Bl = g_BloT + (size_t)bn * 128 * DIM;

    float acc[2][4][4];
    #pragma unroll
    for (int i = 0; i < 2; i++)
        #pragma unroll
        for (int j = 0; j < 4; j++)
            #pragma unroll
            for (int k = 0; k < 4; k++) acc[i][j][k] = 0.f;

    const uint32_t a_row = lane & 15, a_c8 = (lane >> 4) << 3;
    const uint32_t b_n   = (lane & 7) + ((lane >> 4) << 3);
    const uint32_t b_k8  = ((lane >> 3) & 1) << 3;
    const uint32_t sbase = smem_u32(dsm);
    const uint32_t offA0 = 0 * TILE_B + (wm * 32 + a_row) * (SSTRIDE * 2) + a_c8 * 2;
    const uint32_t offA1 = 1 * TILE_B + (wm * 32 + a_row) * (SSTRIDE * 2) + a_c8 * 2;
    const uint32_t offB0 = 2 * TILE_B + (wn * 32 + b_n) * (SSTRIDE * 2) + b_k8 * 2;
    const uint32_t offB1 = 3 * TILE_B + (wn * 32 + b_n) * (SSTRIDE * 2) + b_k8 * 2;

    int ar[2], ac[2];
    #pragma unroll
    for (int i = 0; i < 2; i++) {
        int l = tid + i * 512;
        ar[i] = l >> 3; ac[i] = (l & 7) * 4;
    }
    const int br = tid >> 2, bc = (tid & 3) * 8;

    float4 pa[2];
    uint4  pb[2];
    #pragma unroll
    for (int i = 0; i < 2; i++)
        pa[i] = *(const float4*)(Asrc + (size_t)ar[i] * DIM + ac[i]);
    pb[0] = *(const uint4*)(Bh + (size_t)br * DIM + bc);
    pb[1] = *(const uint4*)(Bl + (size_t)br * DIM + bc);

    for (int ch = 0; ch < 16; ch++) {
        char* buf = dsm + (ch & 1) * BUF_B;
        #pragma unroll
        for (int i = 0; i < 2; i++) {
            float4 v = pa[i];
            __nv_bfloat16 h0 = __float2bfloat16(v.x), h1 = __float2bfloat16(v.y);
            __nv_bfloat16 h2 = __float2bfloat16(v.z), h3 = __float2bfloat16(v.w);
            __nv_bfloat16 l0 = __float2bfloat16(v.x - __bfloat162float(h0));
            __nv_bfloat16 l1 = __float2bfloat16(v.y - __bfloat162float(h1));
            __nv_bfloat16 l2 = __float2bfloat16(v.z - __bfloat162float(h2));
            __nv_bfloat16 l3 = __float2bfloat16(v.w - __bfloat162float(h3));
            uint32_t byo = ar[i] * (SSTRIDE * 2) + ac[i] * 2;
            *(__nv_bfloat162*)(buf + 0 * TILE_B + byo)     = __nv_bfloat162(h0, h1);
            *(__nv_bfloat162*)(buf + 0 * TILE_B + byo + 4) = __nv_bfloat162(h2, h3);
            *(__nv_bfloat162*)(buf + 1 * TILE_B + byo)     = __nv_bfloat162(l0, l1);
            *(__nv_bfloat162*)(buf + 1 * TILE_B + byo + 4) = __nv_bfloat162(l2, l3);
        }
        *(uint4*)(buf + 2 * TILE_B + br * (SSTRIDE * 2) + bc * 2) = pb[0];
        *(uint4*)(buf + 3 * TILE_B + br * (SSTRIDE * 2) + bc * 2) = pb[1];
        __syncthreads();

        if (ch < 15) {
            const int kb = (ch + 1) * 32;
            #pragma unroll
            for (int i = 0; i < 2; i++)
                pa[i] = *(const float4*)(Asrc + (size_t)ar[i] * DIM + kb + ac[i]);
            pb[0] = *(const uint4*)(Bh + (size_t)br * DIM + kb + bc);
            pb[1] = *(const uint4*)(Bl + (size_t)br * DIM + kb + bc);
        }

        const uint32_t bb = sbase + (ch & 1) * BUF_B;
        #pragma unroll
        for (int ks = 0; ks < 2; ks++) {
            const uint32_t ko = ks * 16 * 2;
            uint32_t ah[2][4], al[2][4], bh[4][2], bl[4][2];
            #pragma unroll
            for (int mi = 0; mi < 2; mi++) {
                uint32_t off = mi * 16 * SSTRIDE * 2 + ko;
                ldm_x4(ah[mi][0], ah[mi][1], ah[mi][2], ah[mi][3], bb + offA0 + off);
                ldm_x4(al[mi][0], al[mi][1], al[mi][2], al[mi][3], bb + offA1 + off);
            }
            #pragma unroll
            for (int nh = 0; nh < 2; nh++) {
                uint32_t off = nh * 16 * SSTRIDE * 2 + ko;
                ldm_x4(bh[nh*2][0], bh[nh*2][1], bh[nh*2+1][0], bh[nh*2+1][1], bb + offB0 + off);
                ldm_x4(bl[nh*2][0], bl[nh*2][1], bl[nh*2+1][0], bl[nh*2+1][1], bb + offB1 + off);
            }
            #pragma unroll
            for (int mi = 0; mi < 2; mi++)
                #pragma unroll
                for (int ni = 0; ni < 4; ni++)
                    mma_16816(acc[mi][ni], ah[mi], bh[ni]);
            #pragma unroll
            for (int mi = 0; mi < 2; mi++)
                #pragma unroll
                for (int ni = 0; ni < 4; ni++)
                    mma_16816(acc[mi][ni], ah[mi], bl[ni]);
            #pragma unroll
            for (int mi = 0; mi < 2; mi++)
                #pragma unroll
                for (int ni = 0; ni < 4; ni++)
                    mma_16816(acc[mi][ni], al[mi], bh[ni]);
        }
    }

    const int qr = lane >> 2, qc = (lane & 3) * 2;
    #pragma unroll
    for (int ni = 0; ni < 4; ni++) {
        int col = bn * 128 + wn * 32 + ni * 8 + qc;
        float2 b = *(const float2*)(bias + col);
        #pragma unroll
        for (int mi = 0; mi < 2; mi++) {
            int row = bm * 128 + wm * 32 + mi * 16 + qr;
            float2 v0 = make_float2(acc[mi][ni][0] + b.x, acc[mi][ni][1] + b.y);
            float2 v1 = make_float2(acc[mi][ni][2] + b.x, acc[mi][ni][3] + b.y);
            *(float2*)(C + (size_t)row * DIM + col)       = v0;
            *(float2*)(C + (size_t)(row + 8) * DIM + col) = v1;
        }
    }
}

// ---------------- device: one node of online-softmax attention -------------
__device__ void attn_node(const float* __restrict__ vals, float* __restrict__ out,
                          int node, int lane)
{
    int cnt = min(g_cnt[node], CAP);
    const int* el = g_elist + node * CAP;

    const float* qp = g_q + (size_t)node * DIM;
    float4 q[4];
    #pragma unroll
    for (int j = 0; j < 4; j++) q[j] = *(const float4*)(qp + lane * 4 + j * 128);

    float m = -1e30f, d = 0.f;
    float4 acc[4];
    #pragma unroll
    for (int j = 0; j < 4; j++) acc[j] = make_float4(0.f, 0.f, 0.f, 0.f);

    for (int p = 0; p < cnt; p += 2) {
        const bool has2 = (p + 1 < cnt);
        const float* va = vals + (size_t)el[p] * DIM;
        const float* vb = vals + (size_t)el[has2 ? p + 1 : p] * DIM;

        float4 a[4], b[4];
        #pragma unroll
        for (int j = 0; j < 4; j++) {
            a[j] = ldcs4(va + lane * 4 + j * 128);
            b[j] = ldcs4(vb + lane * 4 + j * 128);
        }

        float sa = 0.f, sb = 0.f;
        #pragma unroll
        for (int j = 0; j < 4; j++) {
            sa += a[j].x * q[j].x + a[j].y * q[j].y + a[j].z * q[j].z + a[j].w * q[j].w;
            sb += b[j].x * q[j].x + b[j].y * q[j].y + b[j].z * q[j].z + b[j].w * q[j].w;
        }
        #pragma unroll
        for (int o = 16; o; o >>= 1) {
            sa += __shfl_xor_sync(0xFFFFFFFFu, sa, o);
            sb += __shfl_xor_sync(0xFFFFFFFFu, sb, o);
        }
        if (!has2) sb = -1e30f;

        float mx = fmaxf(m, fmaxf(sa, sb));
        float r  = expf(m - mx);
        d *= r;
        float wa = expf(sa - mx), wb = expf(sb - mx);
        d += wa + wb;
        #pragma unroll
        for (int j = 0; j < 4; j++) {
            acc[j].x = acc[j].x * r + wa * a[j].x + wb * b[j].x;
            acc[j].y = acc[j].y * r + wa * a[j].y + wb * b[j].y;
            acc[j].z = acc[j].z * r + wa * a[j].z + wb * b[j].z;
            acc[j].w = acc[j].w * r + wa * a[j].w + wb * b[j].w;
        }
        m = mx;
    }

    float inv = 1.0f / fmaxf(d, 1e-12f);
    float* op = out + (size_t)node * DIM;
    #pragma unroll
    for (int j = 0; j < 4; j++) {
        float4 o = make_float4(acc[j].x * inv, acc[j].y * inv,
                               acc[j].z * inv, acc[j].w * inv);
        *(float4*)(op + lane * 4 + j * 128) = o;
    }
}

// ---------------- K1: persistent fused kernel ------------------------------
__global__ __launch_bounds__(512, 1) void fused_kernel(
    const float* __restrict__ Aprev, const float* __restrict__ bias,
    float* __restrict__ C,
    const float* __restrict__ enc,
    const void* __restrict__ c0, const void* __restrict__ c1,
    float* __restrict__ out)
{
    extern __shared__ char dsm[];
    __shared__ int s_t;

    if (blockIdx.x == 0)
        do_detect((const unsigned*)c0, (const unsigned*)c1);

    for (;;) {
        __syncthreads();
        if (threadIdx.x == 0) s_t = atomicAdd(&g_wq, 1);
        __syncthreads();
        const int t = s_t;

        if (t < WQ_GEMM) {
            gemm_tile(dsm, Aprev, bias, C, t >> 2, t & 3);
            __threadfence();
            __syncthreads();
            if (threadIdx.x == 0) atomicAdd(&g_done[t >> 2], 1);
        } else if (t < WQ_BUILD) {
            if (threadIdx.x == 0)
                while (atomicAdd(&g_detect, 0) == 0) {}
            __syncthreads();
            const Cfg cfg = g_cfg;
            const int*  idx  = cfg.idx_is_1 ? (const int*)c1 : (const int*)c0;
            const void* mask = cfg.idx_is_1 ? c0 : c1;
            int e = (t - WQ_GEMM) * 512 + threadIdx.x;
            if (edge_live(mask, e, cfg.mask_byte)) {
                int node = idx[e];
                int pos  = atomicAdd(&g_cnt[node], 1);
                if (pos < CAP) g_elist[node * CAP + pos] = e;
            }
            __threadfence();
            __syncthreads();
            if (threadIdx.x == 0) atomicAdd(&g_build_done, 1);
        } else if (t < WQ_ATTN) {
            const int chunk = t - WQ_BUILD;
            const int bm = chunk >> 2;           // 4 chunks per 128-node bm tile
            if (threadIdx.x == 0) {
                while (atomicAdd(&g_build_done, 0) < 256) {}
                while (atomicAdd(&g_done[bm], 0) < 4) {}
            }
            __syncthreads();
            __threadfence();                      // acquire for q / elist reads
            const int wid = threadIdx.x >> 5, lane = threadIdx.x & 31;
            const int base = chunk * 32 + wid * 2;
            attn_node(enc, out, base, lane);
            attn_node(enc, out, base + 1, lane);
        } else {
            break;
        }
    }
}

// ---------------- launch ---------------------------------------------------
extern "C" void kernel_launch(void* const* d_in, const int* in_sizes, int n_in,
                              void* d_out, int out_size)
{
    const float* enc  = nullptr;
    const void*  c0   = nullptr;
    const void*  c1   = nullptr;
    const float* prev = nullptr;
    const float* Wq   = nullptr;
    const float* bq   = nullptr;
    int n131072 = 0;

    for (int i = 0; i < n_in; i++) {
        switch (in_sizes[i]) {
            case 67108864: enc  = (const float*)d_in[i]; break;
            case 4194304:  prev = (const float*)d_in[i]; break;
            case 262144:   Wq   = (const float*)d_in[i]; break;
            case 512:      bq   = (const float*)d_in[i]; break;
            case 131072:
                if (n131072++ == 0) c0 = d_in[i];
                else                c1 = d_in[i];
                break;
            default: break;
        }
    }

    float* out = (float*)d_out;
    float* q;
    cudaGetSymbolAddress((void**)&q, g_q);

    static int init_done = 0;
    if (!init_done) {
        cudaFuncSetAttribute(fused_kernel,
                             cudaFuncAttributeMaxDynamicSharedMemorySize, GSMEM);
        init_done = 1;
    }

    // K0: weight split + queue-state reset (kernel boundary orders both)
    conv_wq_kernel<<<dim3(16, 16), 256>>>(Wq);

    // K1: persistent fused gemm + build + attn
    fused_kernel<<<152, 512, GSMEM>>>(prev, bq, q, enc, c0, c1, out);
}